// round 2
// baseline (speedup 1.0000x reference)
#include <cuda_runtime.h>
#include <cuda_bf16.h>
#include <math.h>

// ---------------------------------------------------------------------------
// Problem constants (fixed shapes from reference)
// ---------------------------------------------------------------------------
#define BB 2            // batch
#define SS 1024         // seq len
#define WW 64           // context window
#define PP (SS + WW - 1) // padded positions per batch = 1087
#define EE 256          // embed dim
#define FIN 64          // input features
#define FF 1024         // feedforward dim
#define TE 768          // 3*E
#define NH 8            // heads
#define HD 32           // head dim
#define NWIN (BB * SS)      // 2048 windows
#define NROW (NWIN * WW)    // 131072 (window,pos) rows
#define OUTD 10
#define LN_EPS 1e-5f
#define ATT_SCALE 0.17677669529663687f  // 1/sqrt(32)

// ---------------------------------------------------------------------------
// Scratch (static device globals -- allocation-free per harness rules)
// ---------------------------------------------------------------------------
__device__ float g_emb [BB * PP * EE];   // padded embeddings (zeros for pad rows)
__device__ float g_qkv [BB * PP * TE];   // layer-1 qkv, shared across windows
__device__ float g_bufA[(size_t)NROW * EE];
__device__ float g_bufB[(size_t)NROW * EE];
__device__ float g_bufC[(size_t)NROW * FF];  // FFN hidden; reused as qkv2 (stride 768)
__device__ float g_r1  [NWIN * EE];
__device__ float g_r2  [NWIN * EE];
__device__ float g_r3  [NWIN * FF];

// ---------------------------------------------------------------------------
// Embed: g_emb[b][p][e] = (p < W-1) ? 0 : inputs[b][p-63] @ embed_w.T + embed_b
// ---------------------------------------------------------------------------
__global__ void embed_kernel(const float* __restrict__ inputs,
                             const float* __restrict__ ew,
                             const float* __restrict__ eb) {
    int idx = blockIdx.x * blockDim.x + threadIdx.x;
    if (idx >= BB * PP * EE) return;
    int e = idx & (EE - 1);
    int p = (idx / EE) % PP;
    int b = idx / (EE * PP);
    if (p < WW - 1) { g_emb[idx] = 0.f; return; }
    int s = p - (WW - 1);
    const float* xr = inputs + ((size_t)b * SS + s) * FIN;
    const float* wr = ew + (size_t)e * FIN;
    float acc = eb[e];
#pragma unroll 16
    for (int k = 0; k < FIN; k++) acc = fmaf(xr[k], wr[k], acc);
    g_emb[idx] = acc;
}

// ---------------------------------------------------------------------------
// NT SGEMM: C[m,n] = act(sum_k A[m,k]*B[n,k] + bias[n]); A [M,K] rm, B [N,K] rm
// 128x128x8 tile, 256 threads, 8x8 per thread (split 4+4), float4 smem path.
// act: 0 = none, 1 = silu
// ---------------------------------------------------------------------------
#define BM 128
#define BN 128
#define BK 8
__global__ __launch_bounds__(256) void sgemm_nt(
    const float* __restrict__ A, const float* __restrict__ Bm,
    const float* __restrict__ bias, float* __restrict__ C,
    int M, int N, int K, int lda, int ldb, int ldc, int act) {
    __shared__ __align__(16) float As[BK][BM];
    __shared__ __align__(16) float Bs[BK][BN];
    int tid = threadIdx.x;
    int bm = blockIdx.y * BM, bn = blockIdx.x * BN;
    int tx = tid & 15, ty = tid >> 4;
    int lrow = tid >> 1, lk = (tid & 1) * 4;

    float acc[8][8];
#pragma unroll
    for (int i = 0; i < 8; i++)
#pragma unroll
        for (int j = 0; j < 8; j++) acc[i][j] = 0.f;

    for (int k0 = 0; k0 < K; k0 += BK) {
        float4 av = make_float4(0.f, 0.f, 0.f, 0.f);
        int gr = bm + lrow;
        if (gr < M) av = *(const float4*)(A + (size_t)gr * lda + k0 + lk);
        As[lk + 0][lrow] = av.x; As[lk + 1][lrow] = av.y;
        As[lk + 2][lrow] = av.z; As[lk + 3][lrow] = av.w;
        float4 bv = make_float4(0.f, 0.f, 0.f, 0.f);
        int gc = bn + lrow;
        if (gc < N) bv = *(const float4*)(Bm + (size_t)gc * ldb + k0 + lk);
        Bs[lk + 0][lrow] = bv.x; Bs[lk + 1][lrow] = bv.y;
        Bs[lk + 2][lrow] = bv.z; Bs[lk + 3][lrow] = bv.w;
        __syncthreads();
#pragma unroll
        for (int kk = 0; kk < BK; kk++) {
            float ra[8], rb[8];
            *(float4*)&ra[0] = *(const float4*)&As[kk][ty * 4];
            *(float4*)&ra[4] = *(const float4*)&As[kk][64 + ty * 4];
            *(float4*)&rb[0] = *(const float4*)&Bs[kk][tx * 4];
            *(float4*)&rb[4] = *(const float4*)&Bs[kk][64 + tx * 4];
#pragma unroll
            for (int i = 0; i < 8; i++)
#pragma unroll
                for (int j = 0; j < 8; j++)
                    acc[i][j] = fmaf(ra[i], rb[j], acc[i][j]);
        }
        __syncthreads();
    }

#pragma unroll
    for (int i = 0; i < 8; i++) {
        int r = bm + ((i < 4) ? (ty * 4 + i) : (64 + ty * 4 + i - 4));
        if (r >= M) continue;
#pragma unroll
        for (int j = 0; j < 8; j++) {
            int c = bn + ((j < 4) ? (tx * 4 + j) : (64 + tx * 4 + j - 4));
            if (c >= N) continue;
            float v = acc[i][j] + (bias ? bias[c] : 0.f);
            if (act == 1) v = v * (1.f / (1.f + expf(-v)));  // silu
            C[(size_t)r * ldc + c] = v;
        }
    }
}

// ---------------------------------------------------------------------------
// Layer-1 attention: one block per (window n, head h).
// QKV gathered from shared sequence buffer; full 64x64 softmax; out -> g_bufA.
// ---------------------------------------------------------------------------
__global__ __launch_bounds__(256) void attn1_kernel(const float* __restrict__ qkv,
                                                    float* __restrict__ out) {
    int h = blockIdx.x;
    int n = blockIdx.y;
    int b = n >> 10, s = n & (SS - 1);
    int tid = threadIdx.x;
    __shared__ float qs[WW][HD + 1], ks[WW][HD + 1], vs[WW][HD + 1];
    __shared__ float sc[WW][WW + 1];

    size_t base = ((size_t)b * PP + s) * TE + h * HD;
    for (int t = tid; t < WW * HD; t += 256) {
        int wpos = t >> 5, d = t & 31;
        size_t r = base + (size_t)wpos * TE + d;
        qs[wpos][d] = qkv[r];
        ks[wpos][d] = qkv[r + EE];
        vs[wpos][d] = qkv[r + 2 * EE];
    }
    __syncthreads();

    for (int t = tid; t < WW * WW; t += 256) {
        int i = t >> 6, j = t & 63;
        float dsum = 0.f;
#pragma unroll
        for (int d = 0; d < HD; d++) dsum = fmaf(qs[i][d], ks[j][d], dsum);
        sc[i][j] = dsum * ATT_SCALE;
    }
    __syncthreads();

    if (tid < WW) {
        float mx = -1e30f;
        for (int j = 0; j < WW; j++) mx = fmaxf(mx, sc[tid][j]);
        float sum = 0.f;
        for (int j = 0; j < WW; j++) { float e = expf(sc[tid][j] - mx); sc[tid][j] = e; sum += e; }
        float inv = 1.f / sum;
        for (int j = 0; j < WW; j++) sc[tid][j] *= inv;
    }
    __syncthreads();

    for (int t = tid; t < WW * HD; t += 256) {
        int i = t >> 5, d = t & 31;
        float acc = 0.f;
#pragma unroll
        for (int j = 0; j < WW; j++) acc = fmaf(sc[i][j], vs[j][d], acc);
        out[((size_t)n * WW + i) * EE + h * HD + d] = acc;
    }
}

// ---------------------------------------------------------------------------
// Layer-2 attention (pruned): Q only at last window row. One block per (n,h).
// qkv2 rows at stride 768 in g_bufC. Output -> g_r1 [2048, 256].
// ---------------------------------------------------------------------------
__global__ __launch_bounds__(64) void attn2_kernel(const float* __restrict__ qkv2,
                                                   float* __restrict__ out) {
    int h = blockIdx.x;
    int n = blockIdx.y;
    int tid = threadIdx.x;
    __shared__ float ks[WW][HD + 1], vs[WW][HD + 1];
    __shared__ float q[HD], p[WW];

    size_t base = (size_t)n * WW * TE + h * HD;
    for (int t = tid; t < WW * HD; t += 64) {
        int wpos = t >> 5, d = t & 31;
        size_t r = base + (size_t)wpos * TE + d;
        ks[wpos][d] = qkv2[r + EE];
        vs[wpos][d] = qkv2[r + 2 * EE];
    }
    if (tid < HD) q[tid] = qkv2[base + (size_t)(WW - 1) * TE + tid];
    __syncthreads();

    {
        float dsum = 0.f;
#pragma unroll
        for (int d = 0; d < HD; d++) dsum = fmaf(q[d], ks[tid][d], dsum);
        p[tid] = dsum * ATT_SCALE;
    }
    __syncthreads();
    if (tid == 0) {
        float mx = -1e30f;
        for (int j = 0; j < WW; j++) mx = fmaxf(mx, p[j]);
        float sum = 0.f;
        for (int j = 0; j < WW; j++) { float e = expf(p[j] - mx); p[j] = e; sum += e; }
        float inv = 1.f / sum;
        for (int j = 0; j < WW; j++) p[j] *= inv;
    }
    __syncthreads();
    if (tid < HD) {
        float acc = 0.f;
#pragma unroll
        for (int j = 0; j < WW; j++) acc = fmaf(p[j], vs[j][tid], acc);
        out[(size_t)n * EE + h * HD + tid] = acc;
    }
}

// ---------------------------------------------------------------------------
// Fused residual-add + LayerNorm. One block (256 thr) per row; E = 256.
// mode 0: residual row = same row index in res
// mode 1: residual = window view of g_emb (row r = n*64+w -> emb[b][s+w])
// mode 2: residual = res row (r*64 + 63)   [layer-2 last-row gather]
// ---------------------------------------------------------------------------
__global__ __launch_bounds__(256) void add_ln_kernel(
    const float* __restrict__ a, const float* __restrict__ res,
    const float* __restrict__ gamma, const float* __restrict__ beta,
    float* __restrict__ out, int mode) {
    int row = blockIdx.x;
    int e = threadIdx.x;
    __shared__ float red[256];

    size_t roff;
    if (mode == 0) roff = (size_t)row * EE;
    else if (mode == 1) {
        int n = row >> 6, w = row & 63;
        int b = n >> 10, s = n & (SS - 1);
        roff = ((size_t)b * PP + s + w) * EE;
    } else {
        roff = ((size_t)row * WW + (WW - 1)) * EE;
    }

    float x = a[(size_t)row * EE + e] + res[roff + e];

    red[e] = x; __syncthreads();
    for (int st = 128; st > 0; st >>= 1) { if (e < st) red[e] += red[e + st]; __syncthreads(); }
    float mean = red[0] * (1.f / EE);
    __syncthreads();
    float d = x - mean;
    red[e] = d * d; __syncthreads();
    for (int st = 128; st > 0; st >>= 1) { if (e < st) red[e] += red[e + st]; __syncthreads(); }
    float var = red[0] * (1.f / EE);
    out[(size_t)row * EE + e] = d * rsqrtf(var + LN_EPS) * gamma[e] + beta[e];
}

// ---------------------------------------------------------------------------
// Head: out[n, o] = y2[n] . head_w[o] + head_b[o]
// ---------------------------------------------------------------------------
__global__ void head_kernel(const float* __restrict__ y,
                            const float* __restrict__ hw,
                            const float* __restrict__ hb,
                            float* __restrict__ out) {
    int idx = blockIdx.x * blockDim.x + threadIdx.x;
    if (idx >= NWIN * OUTD) return;
    int n = idx / OUTD, o = idx % OUTD;
    const float* yr = y + (size_t)n * EE;
    const float* wr = hw + (size_t)o * EE;
    float acc = hb[o];
#pragma unroll 8
    for (int k = 0; k < EE; k++) acc = fmaf(yr[k], wr[k], acc);
    out[idx] = acc;
}

// ---------------------------------------------------------------------------
// Host launch
// ---------------------------------------------------------------------------
static inline dim3 gemm_grid(int M, int N) {
    return dim3((N + BN - 1) / BN, (M + BM - 1) / BM);
}

extern "C" void kernel_launch(void* const* d_in, const int* in_sizes, int n_in,
                              void* d_out, int out_size) {
    const float* inputs     = (const float*)d_in[0];
    const float* embed_w    = (const float*)d_in[1];
    const float* embed_b    = (const float*)d_in[2];
    const float* qkv_w      = (const float*)d_in[3];
    const float* qkv_b      = (const float*)d_in[4];
    const float* attn_out_w = (const float*)d_in[5];
    const float* attn_out_b = (const float*)d_in[6];
    const float* ln1_g      = (const float*)d_in[7];
    const float* ln1_b      = (const float*)d_in[8];
    const float* ffn1_w     = (const float*)d_in[9];
    const float* ffn1_b     = (const float*)d_in[10];
    const float* ffn2_w     = (const float*)d_in[11];
    const float* ffn2_b     = (const float*)d_in[12];
    const float* ln2_g      = (const float*)d_in[13];
    const float* ln2_b      = (const float*)d_in[14];
    const float* head_w     = (const float*)d_in[15];
    const float* head_b     = (const float*)d_in[16];
    float* out = (float*)d_out;

    float *emb, *qkv, *bufA, *bufB, *bufC, *r1, *r2, *r3;
    cudaGetSymbolAddress((void**)&emb,  g_emb);
    cudaGetSymbolAddress((void**)&qkv,  g_qkv);
    cudaGetSymbolAddress((void**)&bufA, g_bufA);
    cudaGetSymbolAddress((void**)&bufB, g_bufB);
    cudaGetSymbolAddress((void**)&bufC, g_bufC);
    cudaGetSymbolAddress((void**)&r1,   g_r1);
    cudaGetSymbolAddress((void**)&r2,   g_r2);
    cudaGetSymbolAddress((void**)&r3,   g_r3);

    // 1. Embedding into padded layout (pads zeroed in-kernel)
    {
        int tot = BB * PP * EE;
        embed_kernel<<<(tot + 255) / 256, 256>>>(inputs, embed_w, embed_b);
    }
    // 2. Layer-1 QKV, shared over windows: [2174,256] @ [768,256]^T
    sgemm_nt<<<gemm_grid(BB * PP, TE), 256>>>(emb, qkv_w, qkv_b, qkv,
                                              BB * PP, TE, EE, EE, EE, TE, 0);
    // 3. Layer-1 attention -> bufA [131072,256]
    attn1_kernel<<<dim3(NH, NWIN), 256>>>(qkv, bufA);
    // 4. Attn out proj: bufA @ Wo^T -> bufB
    sgemm_nt<<<gemm_grid(NROW, EE), 256>>>(bufA, attn_out_w, attn_out_b, bufB,
                                           NROW, EE, EE, EE, EE, EE, 0);
    // 5. x1 = LN1(emb_window + bufB) -> bufA
    add_ln_kernel<<<NROW, 256>>>(bufB, emb, ln1_g, ln1_b, bufA, 1);
    // 6. FFN hidden: silu(x1 @ W1^T + b1) -> bufC [131072,1024]
    sgemm_nt<<<gemm_grid(NROW, FF), 256>>>(bufA, ffn1_w, ffn1_b, bufC,
                                           NROW, FF, EE, EE, EE, FF, 1);
    // 7. FFN out: bufC @ W2^T -> bufB
    sgemm_nt<<<gemm_grid(NROW, EE), 256>>>(bufC, ffn2_w, ffn2_b, bufB,
                                           NROW, EE, FF, FF, FF, EE, 0);
    // 8. x2 = LN2(x1 + bufB) -> bufA
    add_ln_kernel<<<NROW, 256>>>(bufB, bufA, ln2_g, ln2_b, bufA, 0);

    // ---- Layer 2 (output pruned to last window row) ----
    // 9. qkv2 = x2 @ qkv_w[1]^T -> bufC (stride 768)
    sgemm_nt<<<gemm_grid(NROW, TE), 256>>>(bufA, qkv_w + 1 * TE * EE, qkv_b + TE,
                                           bufC, NROW, TE, EE, EE, EE, TE, 0);
    // 10. attention, q = last row only -> r1 [2048,256]
    attn2_kernel<<<dim3(NH, NWIN), 64>>>(bufC, r1);
    // 11. proj: r1 @ Wo2^T -> r2
    sgemm_nt<<<gemm_grid(NWIN, EE), 256>>>(r1, attn_out_w + EE * EE, attn_out_b + EE,
                                           r2, NWIN, EE, EE, EE, EE, EE, 0);
    // 12. y = LN1_l2(x2[last rows] + r2) -> r1
    add_ln_kernel<<<NWIN, 256>>>(r2, bufA, ln1_g + EE, ln1_b + EE, r1, 2);
    // 13. h2 = silu(y @ W1^T + b1) -> r3
    sgemm_nt<<<gemm_grid(NWIN, FF), 256>>>(r1, ffn1_w + FF * EE, ffn1_b + FF,
                                           r3, NWIN, FF, EE, EE, EE, FF, 1);
    // 14. f2 = h2 @ W2^T -> r2
    sgemm_nt<<<gemm_grid(NWIN, EE), 256>>>(r3, ffn2_w + EE * FF, ffn2_b + EE,
                                           r2, NWIN, EE, FF, FF, FF, EE, 0);
    // 15. y2 = LN2_l2(y + f2) -> r1
    add_ln_kernel<<<NWIN, 256>>>(r2, r1, ln2_g + EE, ln2_b + EE, r1, 0);
    // 16. head -> d_out [2048,10]
    head_kernel<<<(NWIN * OUTD + 255) / 256, 256>>>(r1, head_w, head_b, out);
}

// round 5
// speedup vs baseline: 2.5459x; 2.5459x over previous
#include <cuda_runtime.h>
#include <cuda_bf16.h>
#include <math.h>
#include <stdint.h>

// ---------------------------------------------------------------------------
// Problem constants
// ---------------------------------------------------------------------------
#define BB 2
#define SS 1024
#define WW 64
#define PP (SS + WW - 1)   // 1087
#define EE 256
#define FIN 64
#define FF 1024
#define TE 768
#define NH 8
#define HD 32
#define NWIN (BB * SS)     // 2048
#define NROW (NWIN * WW)   // 131072
#define OUTD 10
#define LN_EPS 1e-5f
#define ATT_SCALE 0.17677669529663687f

// ---------------------------------------------------------------------------
// Scratch
// ---------------------------------------------------------------------------
__device__ float g_emb  [BB * PP * EE];
__device__ float g_qkv  [BB * PP * TE];
__device__ float g_bufA [(size_t)NROW * EE];
__device__ float g_bufB [(size_t)NROW * EE];
__device__ float g_bufC [(size_t)NROW * FF];   // FFN hidden; later KV2 (stride 512)
__device__ float g_xlast[NWIN * EE];
__device__ float g_r1   [NWIN * EE];
__device__ float g_r2   [NWIN * EE];
__device__ float g_r3   [NWIN * FF];

// ---------------------------------------------------------------------------
// TF32 tensor-core GEMM (NT): C[m,n] = act(sum_k A[m,k]*B[n,k] + bias[n])
// A [M,K] row-major, B [N,K] row-major. 128x128 tile, BK=16, double-buffered
// cp.async. 256 threads = 8 warps (2x4), warp tile 64x32, mma m16n8k8 tf32.
// Requires: K % 16 == 0, N % 128 == 0. M arbitrary (clamped loads, guarded
// stores). act: 0 none, 1 silu.
// ---------------------------------------------------------------------------
#define TBK 16
#define SMS 20   // smem row stride (16 + 4 pad) -> conflict-free fragments

__device__ __forceinline__ uint32_t f2tf(float f) {
    uint32_t r;
    asm("cvt.rna.tf32.f32 %0, %1;" : "=r"(r) : "f"(f));
    return r;
}

__device__ __forceinline__ void mma_tf32(float* c, const uint32_t* a, const uint32_t* b) {
    asm volatile(
        "mma.sync.aligned.m16n8k8.row.col.f32.tf32.tf32.f32 "
        "{%0,%1,%2,%3},{%4,%5,%6,%7},{%8,%9},{%0,%1,%2,%3};"
        : "+f"(c[0]), "+f"(c[1]), "+f"(c[2]), "+f"(c[3])
        : "r"(a[0]), "r"(a[1]), "r"(a[2]), "r"(a[3]), "r"(b[0]), "r"(b[1]));
}

__device__ __forceinline__ void cp16(void* s, const void* g) {
    uint32_t sa = (uint32_t)__cvta_generic_to_shared(s);
    asm volatile("cp.async.cg.shared.global [%0], [%1], 16;" :: "r"(sa), "l"(g));
}

__global__ __launch_bounds__(256) void tgemm(
    const float* __restrict__ A, const float* __restrict__ B,
    const float* __restrict__ bias, float* __restrict__ C,
    int M, int N, int K, int lda, int ldb, int ldc, int act) {
    __shared__ __align__(16) float As[2][128][SMS];
    __shared__ __align__(16) float Bs[2][128][SMS];
    const int tid = threadIdx.x;
    const int bm = blockIdx.y * 128, bn = blockIdx.x * 128;
    const int lane = tid & 31, wid = tid >> 5;
    const int wm = (wid >> 2) * 64, wn = (wid & 3) * 32;
    const int g = lane >> 2, t4 = lane & 3;

    float acc[4][4][4];
#pragma unroll
    for (int i = 0; i < 4; i++)
#pragma unroll
        for (int j = 0; j < 4; j++)
#pragma unroll
            for (int k = 0; k < 4; k++) acc[i][j][k] = 0.f;

    const int T = K / TBK;

    // load row/col for this thread's 2 float4s per matrix
    const int r0i = tid >> 2, c4i = (tid & 3) << 2;
    const int r1i = (tid + 256) >> 2, c4i2 = ((tid + 256) & 3) << 2;

    // prologue: tile 0
    {
        int ga = bm + r0i; if (ga >= M) ga = M - 1;
        cp16(&As[0][r0i][c4i], A + (size_t)ga * lda + c4i);
        int gb = bm + r1i; if (gb >= M) gb = M - 1;
        cp16(&As[0][r1i][c4i2], A + (size_t)gb * lda + c4i2);
        cp16(&Bs[0][r0i][c4i],  B + (size_t)(bn + r0i) * ldb + c4i);
        cp16(&Bs[0][r1i][c4i2], B + (size_t)(bn + r1i) * ldb + c4i2);
        asm volatile("cp.async.commit_group;");
    }

    for (int t = 0; t < T; t++) {
        const int cur = t & 1;
        if (t + 1 < T) {
            const int k0 = (t + 1) * TBK;
            const int nxt = cur ^ 1;
            int ga = bm + r0i; if (ga >= M) ga = M - 1;
            cp16(&As[nxt][r0i][c4i], A + (size_t)ga * lda + k0 + c4i);
            int gb = bm + r1i; if (gb >= M) gb = M - 1;
            cp16(&As[nxt][r1i][c4i2], A + (size_t)gb * lda + k0 + c4i2);
            cp16(&Bs[nxt][r0i][c4i],  B + (size_t)(bn + r0i) * ldb + k0 + c4i);
            cp16(&Bs[nxt][r1i][c4i2], B + (size_t)(bn + r1i) * ldb + k0 + c4i2);
            asm volatile("cp.async.commit_group;");
            asm volatile("cp.async.wait_group 1;");
        } else {
            asm volatile("cp.async.wait_group 0;");
        }
        __syncthreads();

#pragma unroll
        for (int ks = 0; ks < 2; ks++) {
            const int kb = ks * 8;
            uint32_t af[4][4], bf[4][2];
#pragma unroll
            for (int mt = 0; mt < 4; mt++) {
                const int r = wm + mt * 16;
                af[mt][0] = f2tf(As[cur][r + g][kb + t4]);
                af[mt][1] = f2tf(As[cur][r + g + 8][kb + t4]);
                af[mt][2] = f2tf(As[cur][r + g][kb + t4 + 4]);
                af[mt][3] = f2tf(As[cur][r + g + 8][kb + t4 + 4]);
            }
#pragma unroll
            for (int nt = 0; nt < 4; nt++) {
                bf[nt][0] = f2tf(Bs[cur][wn + nt * 8 + g][kb + t4]);
                bf[nt][1] = f2tf(Bs[cur][wn + nt * 8 + g][kb + t4 + 4]);
            }
#pragma unroll
            for (int mt = 0; mt < 4; mt++)
#pragma unroll
                for (int nt = 0; nt < 4; nt++)
                    mma_tf32(acc[mt][nt], af[mt], bf[nt]);
        }
        __syncthreads();
    }

    // epilogue
#pragma unroll
    for (int mt = 0; mt < 4; mt++) {
        const int rA = bm + wm + mt * 16 + g;
        const int rB = rA + 8;
#pragma unroll
        for (int nt = 0; nt < 4; nt++) {
            const int c = bn + wn + nt * 8 + 2 * t4;
            const float b0 = bias ? bias[c] : 0.f;
            const float b1 = bias ? bias[c + 1] : 0.f;
            float v0 = acc[mt][nt][0] + b0, v1 = acc[mt][nt][1] + b1;
            float v2 = acc[mt][nt][2] + b0, v3 = acc[mt][nt][3] + b1;
            if (act == 1) {
                v0 = v0 / (1.f + __expf(-v0));
                v1 = v1 / (1.f + __expf(-v1));
                v2 = v2 / (1.f + __expf(-v2));
                v3 = v3 / (1.f + __expf(-v3));
            }
            if (rA < M) { float2 p = make_float2(v0, v1); *(float2*)&C[(size_t)rA * ldc + c] = p; }
            if (rB < M) { float2 p = make_float2(v2, v3); *(float2*)&C[(size_t)rB * ldc + c] = p; }
        }
    }
}

// ---------------------------------------------------------------------------
// Zero pad rows of g_emb (positions 0..W-2 per batch)
// ---------------------------------------------------------------------------
__global__ void zero_pad_kernel() {
    int idx = blockIdx.x * blockDim.x + threadIdx.x;
    if (idx >= BB * (WW - 1) * EE) return;
    int e = idx & (EE - 1);
    int p = (idx >> 8) % (WW - 1);
    int b = idx / ((WW - 1) * EE);
    g_emb[((size_t)b * PP + p) * EE + e] = 0.f;
}

// ---------------------------------------------------------------------------
// Layer-1 attention, full 64x64 per (window, head). Parallel softmax.
// ---------------------------------------------------------------------------
__global__ __launch_bounds__(256) void attn1_kernel(const float* __restrict__ qkv,
                                                    float* __restrict__ out) {
    int h = blockIdx.x;
    int n = blockIdx.y;
    int b = n >> 10, s = n & (SS - 1);
    int tid = threadIdx.x;
    __shared__ float qs[WW][HD + 1], ks[WW][HD + 1], vs[WW][HD + 1];
    __shared__ float sc[WW][WW + 1];

    size_t base = ((size_t)b * PP + s) * TE + h * HD;
    for (int t = tid; t < WW * HD; t += 256) {
        int wpos = t >> 5, d = t & 31;
        size_t r = base + (size_t)wpos * TE + d;
        qs[wpos][d] = qkv[r];
        ks[wpos][d] = qkv[r + EE];
        vs[wpos][d] = qkv[r + 2 * EE];
    }
    __syncthreads();

    for (int t = tid; t < WW * WW; t += 256) {
        int i = t >> 6, j = t & 63;
        float dsum = 0.f;
#pragma unroll
        for (int d = 0; d < HD; d++) dsum = fmaf(qs[i][d], ks[j][d], dsum);
        sc[i][j] = dsum * ATT_SCALE;
    }
    __syncthreads();

    // softmax: thread tid -> row tid>>2, 16 cols per thread, reduce over 4 lanes
    {
        int row = tid >> 2, part = tid & 3;
        float mx = -1e30f;
#pragma unroll
        for (int j = 0; j < 16; j++) mx = fmaxf(mx, sc[row][part * 16 + j]);
        mx = fmaxf(mx, __shfl_xor_sync(0xffffffff, mx, 1));
        mx = fmaxf(mx, __shfl_xor_sync(0xffffffff, mx, 2));
        float sum = 0.f;
#pragma unroll
        for (int j = 0; j < 16; j++) {
            float e = __expf(sc[row][part * 16 + j] - mx);
            sc[row][part * 16 + j] = e;
            sum += e;
        }
        sum += __shfl_xor_sync(0xffffffff, sum, 1);
        sum += __shfl_xor_sync(0xffffffff, sum, 2);
        float inv = 1.f / sum;
#pragma unroll
        for (int j = 0; j < 16; j++) sc[row][part * 16 + j] *= inv;
    }
    __syncthreads();

    for (int t = tid; t < WW * HD; t += 256) {
        int i = t >> 5, d = t & 31;
        float acc = 0.f;
#pragma unroll
        for (int j = 0; j < WW; j++) acc = fmaf(sc[i][j], vs[j][d], acc);
        out[((size_t)n * WW + i) * EE + h * HD + d] = acc;
    }
}

// ---------------------------------------------------------------------------
// Layer-2 attention (pruned): Q from compact [2048,256], KV from [NROW,512].
// ---------------------------------------------------------------------------
__global__ __launch_bounds__(64) void attn2_kernel(const float* __restrict__ q2,
                                                   const float* __restrict__ kv,
                                                   float* __restrict__ out) {
    int h = blockIdx.x;
    int n = blockIdx.y;
    int tid = threadIdx.x;
    __shared__ float ks[WW][HD + 1], vs[WW][HD + 1];
    __shared__ float q[HD], p[WW];

    size_t base = (size_t)n * WW * 512 + h * HD;
    for (int t = tid; t < WW * HD; t += 64) {
        int wpos = t >> 5, d = t & 31;
        size_t r = base + (size_t)wpos * 512 + d;
        ks[wpos][d] = kv[r];
        vs[wpos][d] = kv[r + 256];
    }
    if (tid < HD) q[tid] = q2[(size_t)n * EE + h * HD + tid];
    __syncthreads();

    {
        float dsum = 0.f;
#pragma unroll
        for (int d = 0; d < HD; d++) dsum = fmaf(q[d], ks[tid][d], dsum);
        p[tid] = dsum * ATT_SCALE;
    }
    __syncthreads();
    if (tid < 32) {
        float v = fmaxf(p[tid], p[tid + 32]);
#pragma unroll
        for (int o = 16; o > 0; o >>= 1) v = fmaxf(v, __shfl_xor_sync(0xffffffff, v, o));
        float e0 = __expf(p[tid] - v), e1 = __expf(p[tid + 32] - v);
        float s = e0 + e1;
#pragma unroll
        for (int o = 16; o > 0; o >>= 1) s += __shfl_xor_sync(0xffffffff, s, o);
        float inv = 1.f / s;
        p[tid] = e0 * inv; p[tid + 32] = e1 * inv;
    }
    __syncthreads();
    if (tid < HD) {
        float acc = 0.f;
#pragma unroll
        for (int j = 0; j < WW; j++) acc = fmaf(p[j], vs[j][tid], acc);
        out[(size_t)n * EE + h * HD + tid] = acc;
    }
}

// ---------------------------------------------------------------------------
// Fused residual-add + LayerNorm (E = 256, 256 threads/row, shuffle reduce).
// mode 0: res row = row; mode 1: res = window view of g_emb.
// ---------------------------------------------------------------------------
__global__ __launch_bounds__(256) void add_ln_kernel(
    const float* __restrict__ a, const float* __restrict__ res,
    const float* __restrict__ gamma, const float* __restrict__ beta,
    float* __restrict__ out, int mode) {
    int row = blockIdx.x;
    int e = threadIdx.x;
    int lane = e & 31, w = e >> 5;
    __shared__ float ws[8];

    size_t roff;
    if (mode == 0) roff = (size_t)row * EE;
    else {
        int n = row >> 6, wp = row & 63;
        int b = n >> 10, s = n & (SS - 1);
        roff = ((size_t)b * PP + s + wp) * EE;
    }

    float x = a[(size_t)row * EE + e] + res[roff + e];

    float s1 = x;
#pragma unroll
    for (int o = 16; o > 0; o >>= 1) s1 += __shfl_xor_sync(0xffffffff, s1, o);
    if (lane == 0) ws[w] = s1;
    __syncthreads();
    float tot = 0.f;
#pragma unroll
    for (int i = 0; i < 8; i++) tot += ws[i];
    float mean = tot * (1.f / EE);
    __syncthreads();

    float d = x - mean;
    float s2 = d * d;
#pragma unroll
    for (int o = 16; o > 0; o >>= 1) s2 += __shfl_xor_sync(0xffffffff, s2, o);
    if (lane == 0) ws[w] = s2;
    __syncthreads();
    float tot2 = 0.f;
#pragma unroll
    for (int i = 0; i < 8; i++) tot2 += ws[i];
    float var = tot2 * (1.f / EE);
    out[(size_t)row * EE + e] = d * rsqrtf(var + LN_EPS) * gamma[e] + beta[e];
}

// ---------------------------------------------------------------------------
// Gather last window rows: x2[(n*64+63)] -> xlast[n]
// ---------------------------------------------------------------------------
__global__ void gather_last_kernel(const float* __restrict__ x2,
                                   float* __restrict__ xlast) {
    int idx = blockIdx.x * blockDim.x + threadIdx.x;
    if (idx >= NWIN * EE) return;
    int n = idx >> 8, e = idx & 255;
    xlast[idx] = x2[((size_t)n * WW + (WW - 1)) * EE + e];
}

// ---------------------------------------------------------------------------
// Head: out[n,o] = y[n] . head_w[o] + head_b[o]
// ---------------------------------------------------------------------------
__global__ void head_kernel(const float* __restrict__ y,
                            const float* __restrict__ hw,
                            const float* __restrict__ hb,
                            float* __restrict__ out) {
    int idx = blockIdx.x * blockDim.x + threadIdx.x;
    if (idx >= NWIN * OUTD) return;
    int n = idx / OUTD, o = idx % OUTD;
    const float* yr = y + (size_t)n * EE;
    const float* wr = hw + (size_t)o * EE;
    float acc = hb[o];
#pragma unroll 8
    for (int k = 0; k < EE; k++) acc = fmaf(yr[k], wr[k], acc);
    out[idx] = acc;
}

// ---------------------------------------------------------------------------
// Host launch
// ---------------------------------------------------------------------------
static inline dim3 tgrid(int M, int N) {
    return dim3(N / 128, (M + 127) / 128);
}

extern "C" void kernel_launch(void* const* d_in, const int* in_sizes, int n_in,
                              void* d_out, int out_size) {
    const float* inputs     = (const float*)d_in[0];
    const float* embed_w    = (const float*)d_in[1];
    const float* embed_b    = (const float*)d_in[2];
    const float* qkv_w      = (const float*)d_in[3];
    const float* qkv_b      = (const float*)d_in[4];
    const float* attn_out_w = (const float*)d_in[5];
    const float* attn_out_b = (const float*)d_in[6];
    const float* ln1_g      = (const float*)d_in[7];
    const float* ln1_b      = (const float*)d_in[8];
    const float* ffn1_w     = (const float*)d_in[9];
    const float* ffn1_b     = (const float*)d_in[10];
    const float* ffn2_w     = (const float*)d_in[11];
    const float* ffn2_b     = (const float*)d_in[12];
    const float* ln2_g      = (const float*)d_in[13];
    const float* ln2_b      = (const float*)d_in[14];
    const float* head_w     = (const float*)d_in[15];
    const float* head_b     = (const float*)d_in[16];
    float* out = (float*)d_out;

    float *emb, *qkv, *bufA, *bufB, *bufC, *xlast, *r1, *r2, *r3;
    cudaGetSymbolAddress((void**)&emb,   g_emb);
    cudaGetSymbolAddress((void**)&qkv,   g_qkv);
    cudaGetSymbolAddress((void**)&bufA,  g_bufA);
    cudaGetSymbolAddress((void**)&bufB,  g_bufB);
    cudaGetSymbolAddress((void**)&bufC,  g_bufC);
    cudaGetSymbolAddress((void**)&xlast, g_xlast);
    cudaGetSymbolAddress((void**)&r1,    g_r1);
    cudaGetSymbolAddress((void**)&r2,    g_r2);
    cudaGetSymbolAddress((void**)&r3,    g_r3);

    // 1. zero pad rows, then embedding GEMMs (one per batch, M=1024)
    zero_pad_kernel<<<(BB * (WW - 1) * EE + 255) / 256, 256>>>();
    for (int b = 0; b < BB; b++) {
        tgemm<<<tgrid(SS, EE), 256>>>(inputs + (size_t)b * SS * FIN, embed_w, embed_b,
                                      emb + ((size_t)b * PP + (WW - 1)) * EE,
                                      SS, EE, FIN, FIN, FIN, EE, 0);
    }
    // 2. Layer-1 QKV (shared): [2174,256] x [768,256]^T
    tgemm<<<tgrid(BB * PP, TE), 256>>>(emb, qkv_w, qkv_b, qkv,
                                       BB * PP, TE, EE, EE, EE, TE, 0);
    // 3. attention -> bufA [131072,256]
    attn1_kernel<<<dim3(NH, NWIN), 256>>>(qkv, bufA);
    // 4. attn-out proj -> bufB
    tgemm<<<tgrid(NROW, EE), 256>>>(bufA, attn_out_w, attn_out_b, bufB,
                                    NROW, EE, EE, EE, EE, EE, 0);
    // 5. x1 = LN1(emb_window + bufB) -> bufA
    add_ln_kernel<<<NROW, 256>>>(bufB, emb, ln1_g, ln1_b, bufA, 1);
    // 6. FFN hidden (silu) -> bufC [131072,1024]
    tgemm<<<tgrid(NROW, FF), 256>>>(bufA, ffn1_w, ffn1_b, bufC,
                                    NROW, FF, EE, EE, EE, FF, 1);
    // 7. FFN out -> bufB
    tgemm<<<tgrid(NROW, EE), 256>>>(bufC, ffn2_w, ffn2_b, bufB,
                                    NROW, EE, FF, FF, FF, EE, 0);
    // 8. x2 = LN2(x1 + bufB) -> bufA
    add_ln_kernel<<<NROW, 256>>>(bufB, bufA, ln2_g, ln2_b, bufA, 0);

    // ---- Layer 2 (output pruned) ----
    // 9. gather last rows -> xlast; Q only for last rows -> r2
    gather_last_kernel<<<(NWIN * EE + 255) / 256, 256>>>(bufA, xlast);
    tgemm<<<tgrid(NWIN, EE), 256>>>(xlast, qkv_w + (size_t)TE * EE, qkv_b + TE,
                                    r2, NWIN, EE, EE, EE, EE, EE, 0);
    // 10. KV for all rows -> bufC [131072,512]
    tgemm<<<tgrid(NROW, 512), 256>>>(bufA, qkv_w + (size_t)TE * EE + (size_t)EE * EE,
                                     qkv_b + TE + EE, bufC,
                                     NROW, 512, EE, EE, EE, 512, 0);
    // 11. attention (q last row) -> r1
    attn2_kernel<<<dim3(NH, NWIN), 64>>>(r2, bufC, r1);
    // 12. proj -> r2
    tgemm<<<tgrid(NWIN, EE), 256>>>(r1, attn_out_w + (size_t)EE * EE, attn_out_b + EE,
                                    r2, NWIN, EE, EE, EE, EE, EE, 0);
    // 13. y = LN1_l2(xlast + r2) -> r1
    add_ln_kernel<<<NWIN, 256>>>(r2, xlast, ln1_g + EE, ln1_b + EE, r1, 0);
    // 14. h2 = silu(y @ W1^T) -> r3
    tgemm<<<tgrid(NWIN, FF), 256>>>(r1, ffn1_w + (size_t)FF * EE, ffn1_b + FF,
                                    r3, NWIN, FF, EE, EE, EE, FF, 1);
    // 15. f2 -> r2
    tgemm<<<tgrid(NWIN, EE), 256>>>(r3, ffn2_w + (size_t)EE * FF, ffn2_b + EE,
                                    r2, NWIN, EE, FF, FF, FF, EE, 0);
    // 16. y2 = LN2_l2(y + f2) -> r1
    add_ln_kernel<<<NWIN, 256>>>(r2, r1, ln2_g + EE, ln2_b + EE, r1, 0);
    // 17. head -> d_out
    head_kernel<<<(NWIN * OUTD + 255) / 256, 256>>>(r1, head_w, head_b, out);
}